// round 5
// baseline (speedup 1.0000x reference)
#include <cuda_runtime.h>

// CostVolumeCorrelationLayer: B=8, H=W=128, C=128, maxDisp=4 -> 81 displacements
// out[b,y,x, dy*9+dx] = leaky_relu( mean_c( F1[b,y,x,c] * F2pad[b,y+dy,x+dx,c] ), 0.1 )
//
// Round-5: channel-pair f32x2 packing.
//  - acc[px][dx] holds (sum over even ch, sum over odd ch); final = lo+hi.
//  - smem rows = channel PAIRS, elements = px as float2 (8B). Every FFMA2
//    operand is a natural 8B half of an LDS.128 -> zero re-pairing MOVs.
//  - row stride RLEN=138 f2 (1104B, 16B aligned); XOR swizzle on f4 index
//    sigma(i) = i ^ ((i>>3)&1) makes both the stride-2-f4 compute loads and
//    the fill STS.64 conflict-free.
//  - CCH=32 channels/chunk, 4 chunks, monolithic fill/compute phases.

#define BB 8
#define HH 128
#define WW 128
#define CC_TOT 128
#define KDISP 81

#define CCH 32
#define NCHUNK (CC_TOT / CCH)    // 4
#define NCP (CCH / 2)            // 16 channel-pair rows per chunk
#define NTHREADS 576             // 18 warps = (row 0..1, dy 0..8)
#define ROWS_PER_CTA 2
#define F2ROWS 10

#define RLEN 138                 // float2 per row; 138*8=1104B, 16B-aligned rows
#define F2_ULL (F2ROWS * NCP * RLEN)          // 22080 ull
#define F1_ULL (ROWS_PER_CTA * NCP * RLEN)    // 4416 ull
#define SMEM_BYTES ((F2_ULL + F1_ULL) * 8)    // 211968 B

using ull = unsigned long long;

__device__ __forceinline__ void ffma2(ull &acc, ull a, ull b) {
    asm("fma.rn.f32x2 %0, %1, %2, %0;" : "+l"(acc) : "l"(a), "l"(b));
}
__device__ __forceinline__ int swz4(int i) { return i ^ ((i >> 3) & 1); }
// element (f2) position for pixel-index pxi within a row
__device__ __forceinline__ int spos(int pxi) { return swz4(pxi >> 1) * 2 + (pxi & 1); }

__global__ __launch_bounds__(NTHREADS, 1)
void corr_kernel(const float* __restrict__ F1,
                 const float* __restrict__ F2,
                 float* __restrict__ out)
{
    extern __shared__ ull smemu[];
    ull* F2u = smemu;            // [10][NCP][RLEN]
    ull* F1u = smemu + F2_ULL;   // [2][NCP][RLEN]

    const int y0  = blockIdx.x * 2;
    const int b   = blockIdx.y;
    const int tid = threadIdx.x;
    const int w   = tid >> 5;
    const int g   = tid & 31;
    const int row = (w >= 9) ? 1 : 0;
    const int dy  = w - 9 * row;

    // per-lane swizzled f4 (ulonglong2) load indices: f4 2g+j, j=0..5
    int vj[6];
#pragma unroll
    for (int j = 0; j < 6; j++) vj[j] = swz4(2 * g + j);

    ull acc[4][9];
#pragma unroll
    for (int i = 0; i < 4; i++)
#pragma unroll
        for (int dx = 0; dx < 9; dx++) acc[i][dx] = 0ull;

    for (int ck = 0; ck < NCHUNK; ck++) {
        const int c0 = ck * CCH;
        __syncthreads();   // previous chunk's compute done before refill

        // ---- F2 fill: LDG.128 (4 ch @ 1 px), coalesced; 2x STS.64 to cpair rows ----
        // q -> xi=q&3 (px-in-block), cq=(q>>2)&7 (channel quad), rb=q>>5 -> (r, xb)
        for (int q = tid; q < F2ROWS * 136 * 8; q += NTHREADS) {
            int xi = q & 3;
            int cq = (q >> 2) & 7;
            int rb = q >> 5;
            int r  = rb / 34;
            int xb = rb - r * 34;
            int pxi = xb * 4 + xi;        // 0..135
            int x   = pxi - 4;
            int yy  = y0 + r - 4;
            ull v0 = 0ull, v1 = 0ull;
            if (yy >= 0 && yy < HH && x >= 0 && x < WW) {
                ulonglong2 v = *reinterpret_cast<const ulonglong2*>(
                    F2 + (((size_t)(b * HH + yy) * WW + x) * CC_TOT + c0 + 4 * cq));
                v0 = v.x; v1 = v.y;       // (c, c+1), (c+2, c+3)
            }
            int e = spos(pxi);
            ull* dst = F2u + ((size_t)r * NCP + 2 * cq) * RLEN + e;
            dst[0]    = v0;               // cpair row 2cq
            dst[RLEN] = v1;               // cpair row 2cq+1
        }
        // ---- F1 fill: 2 rows, pxi 0..127 ----
        for (int q = tid; q < ROWS_PER_CTA * 128 * 8; q += NTHREADS) {
            int xi = q & 3;
            int cq = (q >> 2) & 7;
            int rb = q >> 5;
            int r2 = rb >> 5;
            int xb = rb & 31;
            int pxi = xb * 4 + xi;
            ulonglong2 v = *reinterpret_cast<const ulonglong2*>(
                F1 + (((size_t)(b * HH + y0 + r2) * WW + pxi) * CC_TOT + c0 + 4 * cq));
            int e = spos(pxi);
            ull* dst = F1u + ((size_t)r2 * NCP + 2 * cq) * RLEN + e;
            dst[0]    = v.x;
            dst[RLEN] = v.y;
        }
        __syncthreads();

        // ---- compute: 16 channel-pair rows ----
        const ulonglong2* f2b = reinterpret_cast<const ulonglong2*>(
            F2u + (size_t)(row + dy) * NCP * RLEN);
        const ulonglong2* f1b = reinterpret_cast<const ulonglong2*>(
            F1u + (size_t)row * NCP * RLEN);

#pragma unroll 2
        for (int cp = 0; cp < NCP; cp++) {
            const ulonglong2* f2r = f2b + (size_t)cp * (RLEN / 2);
            const ulonglong2* f1r = f1b + (size_t)cp * (RLEN / 2);

            ulonglong2 A0 = f1r[vj[0]];   // F1 px 4g..4g+1 (ch pair)
            ulonglong2 A1 = f1r[vj[1]];   // F1 px 4g+2..4g+3
            ull a[4] = { A0.x, A0.y, A1.x, A1.y };

            // first half: V f4 0..2 -> window f2 t = 0..5 (pxi 4g..4g+5)
            {
                ulonglong2 V0 = f2r[vj[0]];
                ulonglong2 V1 = f2r[vj[1]];
                ulonglong2 V2 = f2r[vj[2]];
                ull t0 = V0.x, t1 = V0.y, t2 = V1.x, t3 = V1.y, t4 = V2.x, t5 = V2.y;
                // acc[i][t-i] += a[i] * vt  for valid i (t-i = dx in 0..8)
                ffma2(acc[0][0], a[0], t0);
                ffma2(acc[0][1], a[0], t1); ffma2(acc[1][0], a[1], t1);
                ffma2(acc[0][2], a[0], t2); ffma2(acc[1][1], a[1], t2); ffma2(acc[2][0], a[2], t2);
                ffma2(acc[0][3], a[0], t3); ffma2(acc[1][2], a[1], t3); ffma2(acc[2][1], a[2], t3); ffma2(acc[3][0], a[3], t3);
                ffma2(acc[0][4], a[0], t4); ffma2(acc[1][3], a[1], t4); ffma2(acc[2][2], a[2], t4); ffma2(acc[3][1], a[3], t4);
                ffma2(acc[0][5], a[0], t5); ffma2(acc[1][4], a[1], t5); ffma2(acc[2][3], a[2], t5); ffma2(acc[3][2], a[3], t5);
            }
            // second half: V f4 3..5 -> window f2 t = 6..11 (pxi 4g+6..4g+11)
            {
                ulonglong2 V3 = f2r[vj[3]];
                ulonglong2 V4 = f2r[vj[4]];
                ulonglong2 V5 = f2r[vj[5]];
                ull t6 = V3.x, t7 = V3.y, t8 = V4.x, t9 = V4.y, t10 = V5.x, t11 = V5.y;
                ffma2(acc[0][6], a[0], t6); ffma2(acc[1][5], a[1], t6); ffma2(acc[2][4], a[2], t6); ffma2(acc[3][3], a[3], t6);
                ffma2(acc[0][7], a[0], t7); ffma2(acc[1][6], a[1], t7); ffma2(acc[2][5], a[2], t7); ffma2(acc[3][4], a[3], t7);
                ffma2(acc[0][8], a[0], t8); ffma2(acc[1][7], a[1], t8); ffma2(acc[2][6], a[2], t8); ffma2(acc[3][5], a[3], t8);
                ffma2(acc[1][8], a[1], t9); ffma2(acc[2][7], a[2], t9); ffma2(acc[3][6], a[3], t9);
                ffma2(acc[2][8], a[2], t10); ffma2(acc[3][7], a[3], t10);
                ffma2(acc[3][8], a[3], t11);
            }
        }
    }

    // ---- finalize: (lo+hi)*inv, leaky relu; stage both rows; coalesced copy ----
    __syncthreads();
    {
        float* ob = reinterpret_cast<float*>(smemu);   // 2*128*81 floats = 82944 B
        const float inv = 1.0f / 128.0f;
#pragma unroll
        for (int i = 0; i < 4; i++) {
            int px = 4 * g + i;
#pragma unroll
            for (int dx = 0; dx < 9; dx++) {
                ull a = acc[i][dx];
                float v = (__uint_as_float((unsigned int)a) +
                           __uint_as_float((unsigned int)(a >> 32))) * inv;
                v = v > 0.f ? v : 0.1f * v;
                ob[(size_t)row * WW * KDISP + px * KDISP + dy * 9 + dx] = v;
            }
        }
    }
    __syncthreads();
    {
        const float4* obv = reinterpret_cast<const float4*>(smemu);
        float4* ov = reinterpret_cast<float4*>(
            out + ((size_t)(b * HH + y0)) * WW * KDISP);
        for (int q = tid; q < (ROWS_PER_CTA * WW * KDISP) / 4; q += NTHREADS) {
            ov[q] = obv[q];
        }
    }
}

extern "C" void kernel_launch(void* const* d_in, const int* in_sizes, int n_in,
                              void* d_out, int out_size)
{
    const float* F1 = (const float*)d_in[0];
    const float* F2 = (const float*)d_in[1];
    float* out = (float*)d_out;

    cudaFuncSetAttribute(corr_kernel, cudaFuncAttributeMaxDynamicSharedMemorySize, SMEM_BYTES);

    dim3 grid(HH / ROWS_PER_CTA, BB);   // (y-pair, b)
    dim3 block(NTHREADS);
    corr_kernel<<<grid, block, SMEM_BYTES>>>(F1, F2, out);
}